// round 14
// baseline (speedup 1.0000x reference)
#include <cuda_runtime.h>
#include <cuda_fp16.h>
#include <math.h>
#include <stdint.h>

#define BB 4
#define NN 512
#define BQ 2048
#define KBINS 48
#define PI_F 3.14159265358979f
#define NSPLIT 8

typedef unsigned long long ull;

// ---------------- device scratch ----------------
__device__ __align__(16) __half g_Xh[BQ * 4704];
__device__ __align__(16) uint2 g_list [BQ * NN];
__device__ int   g_cnt [BQ];
__device__ int   g_boff[BQ * 49];
__device__ __align__(16) uint2 g_listo[BQ * NN];
__device__ int   g_cnto[BQ];
__device__ int   g_boffo[BQ * 49];
__device__ __align__(16) __half g_KSh[829440];   // TC weight segments (half)
__device__ __align__(16) float  g_KSf[9344];     // obstacle (96x32) + gemv (3136x2)
__device__ __align__(16) float g_part[NSPLIT * BQ * 64];
__device__ __align__(16) float g_outA[BQ * 96];
__device__ __align__(16) float g_outB[BQ * 96];
__device__ __align__(16) float g_feats[BQ * 96];
__device__ float g_p1[BQ * 2];
__device__ int   g_ctr[4 * 32];                  // split-K completion counters

// half-KS segment offsets (in halves)
#define H1A 0          // 64 x 1984
#define HL1 126976     // 64 x 4704
#define HL2 428032     // 64 x 3136
#define HL3 628736     // 64 x 3136
// float-KS offsets
#define F1B 0          // 96 x 32 row-major (obstacle)
#define FL4 3072       // 3136 x 2 row-major (gemv)

// quarter-thread prefix for steer
#define SQ0 31744
#define SQ1 107008
#define SQ2 157184
#define SQ3 207360
#define SQ4 210432
#define SQ5 216704
#define STEER_BLOCKS ((SQ5 + 255)/256)   // 847

// ---------------- kernels ----------------

__global__ void k_prep(const float* __restrict__ p0, const float* __restrict__ v0,
                       const float* __restrict__ a, const float* __restrict__ other,
                       const float* __restrict__ v0enc)
{
    int i = blockIdx.x*blockDim.x + threadIdx.x;
    if (i < 128) g_ctr[i] = 0;
    if (i >= BQ) return;
    float v0x = v0[i*2], v0y = v0[i*2+1];
    float v1x = v0x + 0.1f*a[i*2], v1y = v0y + 0.1f*a[i*2+1];
    g_p1[i*2]   = p0[i*2]   + 0.05f*(v0x+v1x);
    g_p1[i*2+1] = p0[i*2+1] + 0.05f*(v0y+v1y);
    float* f = g_feats + i*40;
    f[0]=v1x; f[1]=v1y;
    #pragma unroll
    for (int c=0;c<3;c++){ f[2+c*2]=other[(i*3+c)*2]; f[3+c*2]=other[(i*3+c)*2+1]; }
    #pragma unroll
    for (int c=0;c<16;c++){ f[8+c*2]=v0enc[(i*16+c)*2]; f[9+c*2]=v0enc[(i*16+c)*2+1]; }
}

// ---- steered-kernel assembly helpers ----
struct SteerArgs { const float* Wc[6]; const float* Ad[6]; const float* Bd[6]; };

template<int O, int I, int COLS, int DOFF>
__device__ __forceinline__ float steer_val_rm(int idx, const float* __restrict__ Wc,
                                              const float* __restrict__ Ad,
                                              const float* __restrict__ Bd,
                                              const float* tc, const float* ts)
{
    constexpr int IV = 2*I;
    int row = idx / COLS, col = idx - (idx/COLS)*COLS;
    float val = 0.f;
    if (row < KBINS*IV) {
        if (col < 2*O) {
            int k = row / IV, iv = row - (row/IV)*IV, i = iv>>1, v = iv&1;
            int o = col>>1, u = col&1;
            float c = tc[k & 15], s = ts[k & 15];
            float R[2][2] = {{c,-s},{s,c}};
            const float* Wb = Wc + (((long long)k*O + o)*I + i)*4;
            val = R[u][0]*(Wb[0]*R[v][0] + Wb[1]*R[v][1])
                + R[u][1]*(Wb[2]*R[v][0] + Wb[3]*R[v][1]);
        }
    } else if (row < KBINS*IV + IV) {
        if (DOFF >= 0 && col >= DOFF && col < DOFF + 2*O) {
            int iv = row - KBINS*IV, i = iv>>1, v = iv&1;
            int oc = col - DOFF, o = oc>>1, u = oc&1;
            if (u == v) val = Ad[o*I+i];
            else        val = (u==0) ? -Bd[o*I+i] : Bd[o*I+i];
        }
    }
    return val;
}

template<int O, int I, int K, bool SEG0>
__device__ __forceinline__ void steer_quarter(int qi, int off,
                                              const float* __restrict__ Wc,
                                              const float* __restrict__ Ad,
                                              const float* __restrict__ Bd,
                                              const float* tc, const float* ts)
{
    constexpr int IV = 2*I;
    constexpr int halfK = K/2;
    int op = qi / halfK, rk = qi - op*halfK;
    int row0 = rk*2;
    float v00=0.f, v01=0.f, v10=0.f, v11=0.f;
    if (row0 < KBINS*IV) {
        if (!SEG0 || op < O) {
            int o = op;
            int k = row0 / IV;
            int i = (row0 - k*IV) >> 1;
            float c = tc[k & 15], s = ts[k & 15];
            const float* Wb = Wc + (((long long)k*O + o)*I + i)*4;
            float w0=Wb[0], w1=Wb[1], w2=Wb[2], w3=Wb[3];
            float ta0 = w0*c + w1*(-s), tb0 = w2*c + w3*(-s);
            float ta1 = w0*s + w1*c,    tb1 = w2*s + w3*c;
            v00 = c*ta0 + (-s)*tb0;  v01 = c*ta1 + (-s)*tb1;
            v10 = s*ta0 + c*tb0;     v11 = s*ta1 + c*tb1;
        }
    } else if (row0 < KBINS*IV + IV) {
        if (!SEG0 || op >= O) {
            int o = SEG0 ? (op - O) : op;
            int i = (row0 - KBINS*IV) >> 1;
            float A = Ad[o*I+i], Bv = Bd[o*I+i];
            v00 = A; v01 = -Bv; v10 = Bv; v11 = A;
        }
    }
    __half* p0 = g_KSh + off + (size_t)(2*op)*K + row0;
    *(__half2*)p0       = __floats2half2_rn(v00, v01);
    *(__half2*)(p0 + K) = __floats2half2_rn(v10, v11);
}

// ---- fused front: compact (blocks 0..511) + steer (blocks 512..) ----
__global__ void k_front(SteerArgs args, const float* __restrict__ box,
                        const float* __restrict__ fmask, const float* __restrict__ bmask)
{
    __shared__ uint2 s_tmp[8][NN];
    __shared__ int s_cnt[8][KBINS];
    __shared__ int s_off[8][KBINS+1];
    __shared__ int s_run[8][KBINS];
    __shared__ float tcs[16], tss[16];
    int blk = blockIdx.x;
    if (blk >= 512) {
        if (threadIdx.x < 16) {
            float th = (threadIdx.x + 0.5f)*(2.0f*PI_F/16.0f) - PI_F;
            tcs[threadIdx.x] = cosf(th);
            tss[threadIdx.x] = sinf(th);
        }
        __syncthreads();
        int gidx = (blk - 512)*256 + threadIdx.x;
        if (gidx >= SQ5) return;
        if (gidx < SQ0) {
            steer_quarter<16,20,1984,true>(gidx, H1A, args.Wc[0], args.Ad[0], args.Bd[0], tcs, tss);
        } else if (gidx < SQ1) {
            steer_quarter<32,48,4704,false>(gidx-SQ0, HL1, args.Wc[2], args.Ad[2], args.Bd[2], tcs, tss);
        } else if (gidx < SQ2) {
            steer_quarter<32,32,3136,false>(gidx-SQ1, HL2, args.Wc[3], args.Ad[3], args.Bd[3], tcs, tss);
        } else if (gidx < SQ3) {
            steer_quarter<32,32,3136,false>(gidx-SQ2, HL3, args.Wc[4], args.Ad[4], args.Bd[4], tcs, tss);
        } else if (gidx < SQ4) {
            int idx = gidx - SQ3;
            g_KSf[F1B + idx] = steer_val_rm<16,1,32,-1>(idx, args.Wc[1], 0, 0, tcs, tss);
        } else {
            int idx = gidx - SQ4;
            g_KSf[FL4 + idx] = steer_val_rm<1,32,2,0>(idx, args.Wc[5], args.Ad[5], args.Bd[5], tcs, tss);
        }
        return;
    }
    // ---- compaction + counting sort ----
    int wIn = threadIdx.x >> 5;
    int lane = threadIdx.x & 31;
    bool fluid = (blk < 256);
    int bx = fluid ? blk : blk - 256;
    int warp = bx*8 + wIn;
    int b = warp >> 9, q = warp & 511;
    const float* src = fluid ? g_p1 : box;
    const float* mrow = (fluid ? fmask : bmask) + (size_t)warp*NN;
    uint2* list = fluid ? g_list : g_listo;
    int* cnt  = fluid ? g_cnt : g_cnto;
    int* boff = fluid ? g_boff : g_boffo;
    float qx = g_p1[(b*NN+q)*2], qy = g_p1[(b*NN+q)*2+1];
    for (int i = lane; i < KBINS; i += 32) { s_cnt[wIn][i] = 0; s_run[wIn][i] = 0; }
    __syncwarp();
    int base = 0;
    for (int c = 0; c < NN; c += 32) {
        int s = c + lane;
        float rx = src[(b*NN+s)*2]   - qx;
        float ry = src[(b*NN+s)*2+1] - qy;
        float d2 = rx*rx + ry*ry;
        float m = mrow[s];
        float win = 1.0f - d2*(1.0f/1600.0f);
        bool on = (win > 0.f) && (m != 0.f);
        float wv = 0.f; int kidx = 0;
        if (on) {
            wv = win*win*win*m;
            float dist = sqrtf(d2 + 1e-9f);
            int rb = (int)(dist*(3.0f/40.0f)); if (rb > 2) rb = 2;
            int tb = ((int)floorf((atan2f(ry,rx) + PI_F)*(16.0f/(2.0f*PI_F)))) & 15;
            kidx = rb*16 + tb;
        }
        unsigned mk = __ballot_sync(0xffffffffu, on);
        if (on) {
            int pos = base + __popc(mk & ((1u<<lane)-1u));
            s_tmp[wIn][pos] = make_uint2(__float_as_uint(wv), (unsigned)((kidx<<16) | s));
        }
        base += __popc(mk);
    }
    __syncwarp();
    for (int e = lane; e < base; e += 32)
        atomicAdd(&s_cnt[wIn][s_tmp[wIn][e].y >> 16], 1);
    __syncwarp();
    if (lane == 0) {
        int acc = 0;
        #pragma unroll
        for (int k = 0; k < KBINS; ++k) { s_off[wIn][k] = acc; acc += s_cnt[wIn][k]; }
        s_off[wIn][KBINS] = acc;
    }
    __syncwarp();
    uint2* lrow = list + (size_t)warp*NN;
    for (int c = 0; c < base; c += 32) {
        int e = c + lane;
        bool valid = e < base;
        unsigned msk = __ballot_sync(0xffffffffu, valid);
        int bin = 0, rank = 0, gcnt = 0; bool lead = false; uint2 pk;
        if (valid) {
            pk = s_tmp[wIn][e];
            bin = pk.y >> 16;
            unsigned grp = __match_any_sync(msk, bin);
            rank = __popc(grp & ((1u<<lane)-1u));
            lead = ((__ffs(grp)-1) == lane);
            gcnt = __popc(grp);
        }
        int runv = valid ? s_run[wIn][bin] : 0;
        __syncwarp();
        if (valid) {
            lrow[s_off[wIn][bin] + runv + rank] = pk;
            if (lead) s_run[wIn][bin] = runv + gcnt;
        }
        __syncwarp();
    }
    for (int k = lane; k < KBINS+1; k += 32) boff[warp*49 + k] = s_off[wIn][k];
    if (lane == 0) cnt[warp] = base;
}

// ---- fluid binning body: dual-accumulator unroll, fp16 output ----
template<int IV, int LD, int NG>
__device__ __forceinline__ void bin_body(const float* __restrict__ feats)
{
    constexpr int HV = IV/2;
    constexpr int T = HV*NG;
    __shared__ uint2 sl[NN];
    __shared__ int sb[KBINS+1];
    int bq = blockIdx.x, tid = threadIdx.x, b = bq >> 9;
    int cnt = g_cnt[bq];
    const uint2* lrow = g_list + (size_t)bq*NN;
    for (int i = tid; i < cnt; i += T) sl[i] = lrow[i];
    for (int i = tid; i < KBINS+1; i += T) sb[i] = g_boff[bq*49 + i];
    __syncthreads();
    int col = tid % HV, grp = tid / HV;
    const float2* fb = (const float2*)feats + (size_t)(b*NN)*HV + col;
    __half* xr = g_Xh + (size_t)bq*LD;
    for (int k = grp; k < KBINS; k += NG) {
        int e = sb[k], e1 = sb[k+1];
        float2 a0 = make_float2(0.f, 0.f), a1 = make_float2(0.f, 0.f);
        for (; e + 2 <= e1; e += 2) {
            uint2 p0 = sl[e], p1 = sl[e+1];
            float2 f0 = fb[(size_t)(p0.y & 0xffff)*HV];
            float2 f1 = fb[(size_t)(p1.y & 0xffff)*HV];
            float w0 = __uint_as_float(p0.x), w1 = __uint_as_float(p1.x);
            a0.x += w0*f0.x; a0.y += w0*f0.y;
            a1.x += w1*f1.x; a1.y += w1*f1.y;
        }
        if (e < e1) {
            uint2 p0 = sl[e];
            float2 f0 = fb[(size_t)(p0.y & 0xffff)*HV];
            float w0 = __uint_as_float(p0.x);
            a0.x += w0*f0.x; a0.y += w0*f0.y;
        }
        *(__half2*)&xr[k*IV + 2*col] = __floats2half2_rn(a0.x + a1.x, a0.y + a1.y);
    }
    for (int i = tid; i < IV; i += T)
        xr[KBINS*IV + i] = __float2half_rn(feats[(size_t)bq*IV + i]);
    for (int i = 49*IV + tid; i < LD; i += T) xr[i] = __float2half_rn(0.f);
}

template<int IV, int LD, int NG>
__global__ void k_bin(const float* __restrict__ feats)
{
    bin_body<IV, LD, NG>(feats);
}

// obstacle binning + obstacle conv fused: writes g_feats cols 0..31 directly
__device__ __forceinline__ void bino_body(const float* __restrict__ box_feats,
                                          const float* __restrict__ KSo)
{
    __shared__ uint2 sl[NN];
    __shared__ float sbf[NN*2];
    __shared__ int sb[KBINS+1];
    __shared__ float sXo[96];
    int bq = blockIdx.x, tid = threadIdx.x, b = bq >> 9;
    int T = blockDim.x;
    int cnt = g_cnto[bq];
    const uint2* lrow = g_listo + (size_t)bq*NN;
    for (int i = tid; i < cnt; i += T) sl[i] = lrow[i];
    for (int i = tid; i < KBINS+1; i += T) sb[i] = g_boffo[bq*49 + i];
    for (int i = tid; i < NN*2; i += T) sbf[i] = box_feats[b*NN*2 + i];
    __syncthreads();
    if (tid < 96) {
        int k = tid >> 1, v = tid & 1;
        float acc = 0.f;
        int e1 = sb[k+1];
        for (int e = sb[k]; e < e1; ++e) {
            uint2 pk = sl[e];
            acc += __uint_as_float(pk.x) * sbf[(pk.y & 0xffff)*2 + v];
        }
        sXo[tid] = acc;
    }
    __syncthreads();
    if (tid < 16) {
        float x = 0.f, y = 0.f;
        #pragma unroll 8
        for (int k = 0; k < 96; ++k) {
            float xv = sXo[k];
            x += xv * KSo[k*32 + 2*tid];
            y += xv * KSo[k*32 + 2*tid + 1];
        }
        float mag = x*x + y*y + 1e-6f;
        float sc = fmaxf(mag - 0.2f, 0.f) / mag;
        g_feats[bq*96 + 2*tid]   = x*sc;
        g_feats[bq*96 + 2*tid+1] = y*sc;
    }
}

__global__ void k_bin1(const float* __restrict__ feats, const float* __restrict__ boxf,
                       const float* __restrict__ KSo)
{
    if (blockIdx.y == 0) bin_body<40, 1984, 12>(feats);
    else                 bino_body(boxf, KSo);
}

// ---- fp16 tensor-core GEMM with fused deterministic split-K epilogue ----
// layer: counter bank. out==nullptr -> stage-1 mode (feats ld 96, col offset 32, no out buffer).
__global__ void k_gemm_mma(const __half* __restrict__ X, const __half* __restrict__ Wt,
                           int inner, int layer,
                           float* __restrict__ out, const float* __restrict__ res)
{
    __shared__ __half As[64][40];
    __shared__ __half Bs[64][40];
    __shared__ int s_old;
    int tid = threadIdx.x, lane = tid & 31, warp = tid >> 5;
    int row0 = blockIdx.x * 64;
    int ntiles = inner / 32;
    int per = (ntiles + NSPLIT - 1) / NSPLIT;
    int t0 = blockIdx.y * per;
    int t1 = min(ntiles, t0 + per);
    int g = lane >> 2, q = lane & 3;

    float acc[8][4];
    #pragma unroll
    for (int b = 0; b < 8; ++b)
        #pragma unroll
        for (int c = 0; c < 4; ++c) acc[b][c] = 0.f;

    for (int t = t0; t < t1; ++t) {
        int kk = t*32;
        #pragma unroll
        for (int r = 0; r < 2; ++r) {
            int idx = tid + r*128;
            int m = idx >> 2, c8 = (idx & 3)*8;
            uint4 v = *(const uint4*)&X[(size_t)(row0+m)*inner + kk + c8];
            *(uint4*)&As[m][c8] = v;
        }
        #pragma unroll
        for (int r = 0; r < 2; ++r) {
            int idx = tid + r*128;
            int n = idx >> 2, c8 = (idx & 3)*8;
            uint4 v = *(const uint4*)&Wt[(size_t)n*inner + kk + c8];
            *(uint4*)&Bs[n][c8] = v;
        }
        __syncthreads();
        #pragma unroll
        for (int k16 = 0; k16 < 2; ++k16) {
            int kb = k16*16;
            int mr = warp*16 + g;
            uint32_t a0 = *(const uint32_t*)&As[mr][kb + 2*q];
            uint32_t a1 = *(const uint32_t*)&As[mr+8][kb + 2*q];
            uint32_t a2 = *(const uint32_t*)&As[mr][kb + 2*q + 8];
            uint32_t a3 = *(const uint32_t*)&As[mr+8][kb + 2*q + 8];
            #pragma unroll
            for (int nt = 0; nt < 8; ++nt) {
                int nc = nt*8 + g;
                uint32_t b0 = *(const uint32_t*)&Bs[nc][kb + 2*q];
                uint32_t b1 = *(const uint32_t*)&Bs[nc][kb + 2*q + 8];
                asm volatile(
                    "mma.sync.aligned.m16n8k16.row.col.f32.f16.f16.f32 "
                    "{%0,%1,%2,%3}, {%4,%5,%6,%7}, {%8,%9}, {%0,%1,%2,%3};"
                    : "+f"(acc[nt][0]), "+f"(acc[nt][1]),
                      "+f"(acc[nt][2]), "+f"(acc[nt][3])
                    : "r"(a0), "r"(a1), "r"(a2), "r"(a3),
                      "r"(b0), "r"(b1));
            }
        }
        __syncthreads();
    }
    float* pb = g_part + ((size_t)blockIdx.y*BQ + row0)*64;
    int r0 = warp*16 + g;
    #pragma unroll
    for (int nt = 0; nt < 8; ++nt) {
        int c = nt*8 + q*2;
        *(float2*)&pb[(size_t)r0*64 + c]     = make_float2(acc[nt][0], acc[nt][1]);
        *(float2*)&pb[(size_t)(r0+8)*64 + c] = make_float2(acc[nt][2], acc[nt][3]);
    }
    // deterministic split-K epilogue: last-arriving block reduces in fixed order
    __threadfence();
    if (tid == 0) s_old = atomicAdd(&g_ctr[layer*32 + blockIdx.x], 1);
    __syncthreads();
    if (s_old != NSPLIT-1) return;
    for (int idx = tid; idx < 64*32; idx += 128) {
        int r = idx >> 5, c = idx & 31;
        int row = row0 + r;
        float x = 0.f, y = 0.f;
        #pragma unroll
        for (int s = 0; s < NSPLIT; ++s) {
            const float* p = g_part + ((size_t)s*BQ + row)*64 + 2*c;
            x += p[0]; y += p[1];
        }
        if (res) { x += res[row*64 + 2*c]; y += res[row*64 + 2*c+1]; }
        if (out) { out[row*64 + 2*c] = x; out[row*64 + 2*c+1] = y; }
        float mag = x*x + y*y + 1e-6f;
        float sc = fmaxf(mag - 0.2f, 0.f) / mag;
        if (out) {
            g_feats[row*64 + 2*c]   = x*sc;
            g_feats[row*64 + 2*c+1] = y*sc;
        } else {
            g_feats[row*96 + 32 + 2*c]   = x*sc;
            g_feats[row*96 + 32 + 2*c+1] = y*sc;
        }
    }
}

// layer 4 GEMV (fp32 weights, fp16 X) fused with final correction
__global__ void k_gemv_final(const __half* __restrict__ X, const float* __restrict__ Wm,
                             int inner, const float* __restrict__ p0,
                             float* __restrict__ dout, int half)
{
    __shared__ float Wsh[3136*2];
    int tid = threadIdx.x;
    for (int i = tid; i < inner*2; i += blockDim.x) Wsh[i] = Wm[i];
    __syncthreads();
    int warp = tid >> 5, lane = tid & 31;
    int row = blockIdx.x*8 + warp;
    const __half* xr = X + (size_t)row*inner;
    float a0 = 0.f, a1 = 0.f;
    for (int k = lane; k < inner; k += 32) {
        float x = __half2float(xr[k]);
        a0 += x*Wsh[k*2];
        a1 += x*Wsh[k*2+1];
    }
    #pragma unroll
    for (int o = 16; o; o >>= 1) {
        a0 += __shfl_down_sync(0xffffffffu, a0, o);
        a1 += __shfl_down_sync(0xffffffffu, a1, o);
    }
    if (lane == 0) {
        float px = g_p1[row*2]   + a0*(1.0f/128.0f);
        float py = g_p1[row*2+1] + a1*(1.0f/128.0f);
        dout[row*2]   = px;
        dout[row*2+1] = py;
        dout[half + row*2]   = (px - p0[row*2])  *10.0f;
        dout[half + row*2+1] = (py - p0[row*2+1])*10.0f;
    }
}

// ---------------- host driver ----------------
extern "C" void kernel_launch(void* const* d_in, const int* in_sizes, int n_in,
                              void* d_out, int out_size)
{
    const float* v0_enc = (const float*)d_in[1];
    const float* p0     = (const float*)d_in[2];
    const float* v0     = (const float*)d_in[3];
    const float* a      = (const float*)d_in[4];
    const float* other  = (const float*)d_in[5];
    const float* box    = (const float*)d_in[6];
    const float* boxf   = (const float*)d_in[7];
    const float* fmask  = (const float*)d_in[8];
    const float* bmask  = (const float*)d_in[9];
    float* dout = (float*)d_out;
    int half = out_size / 2;

    __half *Xh, *KSh; float *KSf, *outA, *outB, *feats;
    cudaGetSymbolAddress((void**)&Xh,    g_Xh);
    cudaGetSymbolAddress((void**)&KSh,   g_KSh);
    cudaGetSymbolAddress((void**)&KSf,   g_KSf);
    cudaGetSymbolAddress((void**)&outA,  g_outA);
    cudaGetSymbolAddress((void**)&outB,  g_outB);
    cudaGetSymbolAddress((void**)&feats, g_feats);

    SteerArgs sa;
    sa.Wc[0] = (const float*)d_in[10]; sa.Ad[0] = (const float*)d_in[12]; sa.Bd[0] = (const float*)d_in[13];
    sa.Wc[1] = (const float*)d_in[11]; sa.Ad[1] = nullptr;                sa.Bd[1] = nullptr;
    sa.Wc[2] = (const float*)d_in[14]; sa.Ad[2] = (const float*)d_in[15]; sa.Bd[2] = (const float*)d_in[16];
    sa.Wc[3] = (const float*)d_in[17]; sa.Ad[3] = (const float*)d_in[18]; sa.Bd[3] = (const float*)d_in[19];
    sa.Wc[4] = (const float*)d_in[20]; sa.Ad[4] = (const float*)d_in[21]; sa.Bd[4] = (const float*)d_in[22];
    sa.Wc[5] = (const float*)d_in[23]; sa.Ad[5] = (const float*)d_in[24]; sa.Bd[5] = (const float*)d_in[25];

    dim3 gg(BQ/64, NSPLIT);   // 32 x 8 = 256 CTAs

    // 1. integrate + 20-ch fluid feats + zero counters
    k_prep<<<(BQ+127)/128, 128>>>(p0, v0, a, other, v0_enc);
    // 2. fused compact (x2) + steer
    k_front<<<512 + STEER_BLOCKS, 256>>>(sa, box, fmask, bmask);
    // 3. stage-1 binning: fluid bin40 + obstacle bin+conv (feats cols 0..31)
    k_bin1<<<dim3(BQ, 2), 240>>>(feats, boxf, KSf+F1B);
    // 4. stage-1 GEMM + fused epilogue -> feats cols 32..95
    k_gemm_mma<<<gg, 128>>>(Xh, KSh+H1A, 1984, 0, nullptr, nullptr);
    // 5. layer 1: 48 -> 32
    k_bin<96,4704,6><<<BQ, 288>>>(feats);
    k_gemm_mma<<<gg, 128>>>(Xh, KSh+HL1, 4704, 1, outB, nullptr);
    // 6. layer 2: 32 -> 32, residual
    k_bin<64,3136,8><<<BQ, 256>>>(feats);
    k_gemm_mma<<<gg, 128>>>(Xh, KSh+HL2, 3136, 2, outA, outB);
    // 7. layer 3: 32 -> 32, residual
    k_bin<64,3136,8><<<BQ, 256>>>(feats);
    k_gemm_mma<<<gg, 128>>>(Xh, KSh+HL3, 3136, 3, outB, outA);
    // 8. layer 4: 32 -> 1 (GEMV fused with final correction)
    k_bin<64,3136,8><<<BQ, 256>>>(feats);
    k_gemv_final<<<BQ/8, 256>>>(Xh, KSf+FL4, 3136, p0, dout, half);
}

// round 15
// speedup vs baseline: 1.1682x; 1.1682x over previous
#include <cuda_runtime.h>
#include <cuda_fp16.h>
#include <math.h>
#include <stdint.h>

#define BB 4
#define NN 512
#define BQ 2048
#define KBINS 48
#define PI_F 3.14159265358979f
#define NSPLIT 8

typedef unsigned long long ull;

// ---------------- device scratch ----------------
__device__ __align__(16) __half g_Xh[BQ * 4704];
__device__ __align__(16) uint2 g_list [BQ * NN];
__device__ int   g_cnt [BQ];
__device__ int   g_boff[BQ * 49];
__device__ __align__(16) uint2 g_listo[BQ * NN];
__device__ int   g_cnto[BQ];
__device__ int   g_boffo[BQ * 49];
__device__ __align__(16) __half g_KSh[829440];   // TC weight segments (half)
__device__ __align__(16) float  g_KSf[9344];     // obstacle (96x32) + gemv (3136x2)
__device__ __align__(16) float g_part[NSPLIT * BQ * 64];
__device__ __align__(16) float g_outA[BQ * 96];
__device__ __align__(16) float g_outB[BQ * 96];
__device__ __align__(16) float g_feats[BQ * 96];
__device__ float g_p1[BQ * 2];

// half-KS segment offsets (in halves)
#define H1A 0          // 64 x 1984
#define HL1 126976     // 64 x 4704
#define HL2 428032     // 64 x 3136
#define HL3 628736     // 64 x 3136
// float-KS offsets
#define F1B 0          // 96 x 32 row-major (obstacle)
#define FL4 3072       // 3136 x 2 row-major (gemv)

// quarter-thread prefix for k_steer_all
#define SQ0 31744
#define SQ1 107008
#define SQ2 157184
#define SQ3 207360
#define SQ4 210432
#define SQ5 216704

// ---------------- kernels ----------------

__global__ void k_prep(const float* __restrict__ p0, const float* __restrict__ v0,
                       const float* __restrict__ a, const float* __restrict__ other,
                       const float* __restrict__ v0enc)
{
    int i = blockIdx.x*blockDim.x + threadIdx.x;
    if (i >= BQ) return;
    float v0x = v0[i*2], v0y = v0[i*2+1];
    float v1x = v0x + 0.1f*a[i*2], v1y = v0y + 0.1f*a[i*2+1];
    g_p1[i*2]   = p0[i*2]   + 0.05f*(v0x+v1x);
    g_p1[i*2+1] = p0[i*2+1] + 0.05f*(v0y+v1y);
    float* f = g_feats + i*40;
    f[0]=v1x; f[1]=v1y;
    #pragma unroll
    for (int c=0;c<3;c++){ f[2+c*2]=other[(i*3+c)*2]; f[3+c*2]=other[(i*3+c)*2+1]; }
    #pragma unroll
    for (int c=0;c<16;c++){ f[8+c*2]=v0enc[(i*16+c)*2]; f[9+c*2]=v0enc[(i*16+c)*2+1]; }
}

// geometry + compaction + stable counting sort by bin. One warp per query.
__global__ void k_compact2(const float* __restrict__ box,
                           const float* __restrict__ fmask, const float* __restrict__ bmask)
{
    __shared__ uint2 s_tmp[8][NN];
    __shared__ int s_cnt[8][KBINS];
    __shared__ int s_off[8][KBINS+1];
    __shared__ int s_run[8][KBINS];
    int wIn = threadIdx.x >> 5;
    int lane = threadIdx.x & 31;
    int warp = blockIdx.x*8 + wIn;
    int b = warp >> 9, q = warp & 511;
    bool fluid = (blockIdx.y == 0);
    const float* src = fluid ? g_p1 : box;
    const float* mrow = (fluid ? fmask : bmask) + (size_t)warp*NN;
    uint2* list = fluid ? g_list : g_listo;
    int* cnt  = fluid ? g_cnt : g_cnto;
    int* boff = fluid ? g_boff : g_boffo;
    float qx = g_p1[(b*NN+q)*2], qy = g_p1[(b*NN+q)*2+1];
    for (int i = lane; i < KBINS; i += 32) { s_cnt[wIn][i] = 0; s_run[wIn][i] = 0; }
    __syncwarp();
    int base = 0;
    for (int c = 0; c < NN; c += 32) {
        int s = c + lane;
        float rx = src[(b*NN+s)*2]   - qx;
        float ry = src[(b*NN+s)*2+1] - qy;
        float d2 = rx*rx + ry*ry;
        float m = mrow[s];
        float win = 1.0f - d2*(1.0f/1600.0f);
        bool on = (win > 0.f) && (m != 0.f);
        float wv = 0.f; int kidx = 0;
        if (on) {
            wv = win*win*win*m;
            float dist = sqrtf(d2 + 1e-9f);
            int rb = (int)(dist*(3.0f/40.0f)); if (rb > 2) rb = 2;
            int tb = ((int)floorf((atan2f(ry,rx) + PI_F)*(16.0f/(2.0f*PI_F)))) & 15;
            kidx = rb*16 + tb;
        }
        unsigned mk = __ballot_sync(0xffffffffu, on);
        if (on) {
            int pos = base + __popc(mk & ((1u<<lane)-1u));
            s_tmp[wIn][pos] = make_uint2(__float_as_uint(wv), (unsigned)((kidx<<16) | s));
        }
        base += __popc(mk);
    }
    __syncwarp();
    for (int e = lane; e < base; e += 32)
        atomicAdd(&s_cnt[wIn][s_tmp[wIn][e].y >> 16], 1);
    __syncwarp();
    if (lane == 0) {
        int acc = 0;
        #pragma unroll
        for (int k = 0; k < KBINS; ++k) { s_off[wIn][k] = acc; acc += s_cnt[wIn][k]; }
        s_off[wIn][KBINS] = acc;
    }
    __syncwarp();
    uint2* lrow = list + (size_t)warp*NN;
    for (int c = 0; c < base; c += 32) {
        int e = c + lane;
        bool valid = e < base;
        unsigned msk = __ballot_sync(0xffffffffu, valid);
        int bin = 0, rank = 0, gcnt = 0; bool lead = false; uint2 pk;
        if (valid) {
            pk = s_tmp[wIn][e];
            bin = pk.y >> 16;
            unsigned grp = __match_any_sync(msk, bin);
            rank = __popc(grp & ((1u<<lane)-1u));
            lead = ((__ffs(grp)-1) == lane);
            gcnt = __popc(grp);
        }
        int runv = valid ? s_run[wIn][bin] : 0;
        __syncwarp();
        if (valid) {
            lrow[s_off[wIn][bin] + runv + rank] = pk;
            if (lead) s_run[wIn][bin] = runv + gcnt;
        }
        __syncwarp();
    }
    for (int k = lane; k < KBINS+1; k += 32) boff[warp*49 + k] = s_off[wIn][k];
    if (lane == 0) cnt[warp] = base;
}

// ---- steered-kernel assembly ----
struct SteerArgs { const float* Wc[6]; const float* Ad[6]; const float* Bd[6]; };

template<int O, int I, int COLS, int DOFF>
__device__ __forceinline__ float steer_val_rm(int idx, const float* __restrict__ Wc,
                                              const float* __restrict__ Ad,
                                              const float* __restrict__ Bd,
                                              const float* tc, const float* ts)
{
    constexpr int IV = 2*I;
    int row = idx / COLS, col = idx - (idx/COLS)*COLS;
    float val = 0.f;
    if (row < KBINS*IV) {
        if (col < 2*O) {
            int k = row / IV, iv = row - (row/IV)*IV, i = iv>>1, v = iv&1;
            int o = col>>1, u = col&1;
            float c = tc[k & 15], s = ts[k & 15];
            float R[2][2] = {{c,-s},{s,c}};
            const float* Wb = Wc + (((long long)k*O + o)*I + i)*4;
            val = R[u][0]*(Wb[0]*R[v][0] + Wb[1]*R[v][1])
                + R[u][1]*(Wb[2]*R[v][0] + Wb[3]*R[v][1]);
        }
    } else if (row < KBINS*IV + IV) {
        if (DOFF >= 0 && col >= DOFF && col < DOFF + 2*O) {
            int iv = row - KBINS*IV, i = iv>>1, v = iv&1;
            int oc = col - DOFF, o = oc>>1, u = oc&1;
            if (u == v) val = Ad[o*I+i];
            else        val = (u==0) ? -Bd[o*I+i] : Bd[o*I+i];
        }
    }
    return val;
}

template<int O, int I, int K, bool SEG0>
__device__ __forceinline__ void steer_quarter(int qi, int off,
                                              const float* __restrict__ Wc,
                                              const float* __restrict__ Ad,
                                              const float* __restrict__ Bd,
                                              const float* tc, const float* ts)
{
    constexpr int IV = 2*I;
    constexpr int halfK = K/2;
    int op = qi / halfK, rk = qi - op*halfK;
    int row0 = rk*2;
    float v00=0.f, v01=0.f, v10=0.f, v11=0.f;
    if (row0 < KBINS*IV) {
        if (!SEG0 || op < O) {
            int o = op;
            int k = row0 / IV;
            int i = (row0 - k*IV) >> 1;
            float c = tc[k & 15], s = ts[k & 15];
            const float* Wb = Wc + (((long long)k*O + o)*I + i)*4;
            float w0=Wb[0], w1=Wb[1], w2=Wb[2], w3=Wb[3];
            float ta0 = w0*c + w1*(-s), tb0 = w2*c + w3*(-s);
            float ta1 = w0*s + w1*c,    tb1 = w2*s + w3*c;
            v00 = c*ta0 + (-s)*tb0;  v01 = c*ta1 + (-s)*tb1;
            v10 = s*ta0 + c*tb0;     v11 = s*ta1 + c*tb1;
        }
    } else if (row0 < KBINS*IV + IV) {
        if (!SEG0 || op >= O) {
            int o = SEG0 ? (op - O) : op;
            int i = (row0 - KBINS*IV) >> 1;
            float A = Ad[o*I+i], Bv = Bd[o*I+i];
            v00 = A; v01 = -Bv; v10 = Bv; v11 = A;
        }
    }
    __half* p0 = g_KSh + off + (size_t)(2*op)*K + row0;
    *(__half2*)p0       = __floats2half2_rn(v00, v01);
    *(__half2*)(p0 + K) = __floats2half2_rn(v10, v11);
}

__global__ void k_steer_all(SteerArgs args)
{
    __shared__ float tc[16], ts[16];
    if (threadIdx.x < 16) {
        float th = (threadIdx.x + 0.5f)*(2.0f*PI_F/16.0f) - PI_F;
        tc[threadIdx.x] = cosf(th);
        ts[threadIdx.x] = sinf(th);
    }
    __syncthreads();
    int gidx = blockIdx.x*blockDim.x + threadIdx.x;
    if (gidx >= SQ5) return;
    if (gidx < SQ0) {
        steer_quarter<16,20,1984,true>(gidx, H1A, args.Wc[0], args.Ad[0], args.Bd[0], tc, ts);
    } else if (gidx < SQ1) {
        steer_quarter<32,48,4704,false>(gidx-SQ0, HL1, args.Wc[2], args.Ad[2], args.Bd[2], tc, ts);
    } else if (gidx < SQ2) {
        steer_quarter<32,32,3136,false>(gidx-SQ1, HL2, args.Wc[3], args.Ad[3], args.Bd[3], tc, ts);
    } else if (gidx < SQ3) {
        steer_quarter<32,32,3136,false>(gidx-SQ2, HL3, args.Wc[4], args.Ad[4], args.Bd[4], tc, ts);
    } else if (gidx < SQ4) {
        int idx = gidx - SQ3;
        g_KSf[F1B + idx] = steer_val_rm<16,1,32,-1>(idx, args.Wc[1], 0, 0, tc, ts);
    } else {
        int idx = gidx - SQ4;
        g_KSf[FL4 + idx] = steer_val_rm<1,32,2,0>(idx, args.Wc[5], args.Ad[5], args.Bd[5], tc, ts);
    }
}

// ---- fluid binning body: dual-accumulator unroll, fp16 output ----
template<int IV, int LD, int NG>
__device__ __forceinline__ void bin_body(const float* __restrict__ feats)
{
    constexpr int HV = IV/2;
    constexpr int T = HV*NG;
    __shared__ uint2 sl[NN];
    __shared__ int sb[KBINS+1];
    int bq = blockIdx.x, tid = threadIdx.x, b = bq >> 9;
    int cnt = g_cnt[bq];
    const uint2* lrow = g_list + (size_t)bq*NN;
    for (int i = tid; i < cnt; i += T) sl[i] = lrow[i];
    for (int i = tid; i < KBINS+1; i += T) sb[i] = g_boff[bq*49 + i];
    __syncthreads();
    int col = tid % HV, grp = tid / HV;
    const float2* fb = (const float2*)feats + (size_t)(b*NN)*HV + col;
    __half* xr = g_Xh + (size_t)bq*LD;
    for (int k = grp; k < KBINS; k += NG) {
        int e = sb[k], e1 = sb[k+1];
        float2 a0 = make_float2(0.f, 0.f), a1 = make_float2(0.f, 0.f);
        for (; e + 2 <= e1; e += 2) {
            uint2 p0 = sl[e], p1 = sl[e+1];
            float2 f0 = fb[(size_t)(p0.y & 0xffff)*HV];
            float2 f1 = fb[(size_t)(p1.y & 0xffff)*HV];
            float w0 = __uint_as_float(p0.x), w1 = __uint_as_float(p1.x);
            a0.x += w0*f0.x; a0.y += w0*f0.y;
            a1.x += w1*f1.x; a1.y += w1*f1.y;
        }
        if (e < e1) {
            uint2 p0 = sl[e];
            float2 f0 = fb[(size_t)(p0.y & 0xffff)*HV];
            float w0 = __uint_as_float(p0.x);
            a0.x += w0*f0.x; a0.y += w0*f0.y;
        }
        *(__half2*)&xr[k*IV + 2*col] = __floats2half2_rn(a0.x + a1.x, a0.y + a1.y);
    }
    for (int i = tid; i < IV; i += T)
        xr[KBINS*IV + i] = __float2half_rn(feats[(size_t)bq*IV + i]);
    for (int i = 49*IV + tid; i < LD; i += T) xr[i] = __float2half_rn(0.f);
}

template<int IV, int LD, int NG>
__global__ void k_bin(const float* __restrict__ feats)
{
    bin_body<IV, LD, NG>(feats);
}

// obstacle binning + obstacle conv fused: writes g_feats cols 0..31 directly
__device__ __forceinline__ void bino_body(const float* __restrict__ box_feats,
                                          const float* __restrict__ KSo)
{
    __shared__ uint2 sl[NN];
    __shared__ float sbf[NN*2];
    __shared__ int sb[KBINS+1];
    __shared__ float sXo[96];
    int bq = blockIdx.x, tid = threadIdx.x, b = bq >> 9;
    int T = blockDim.x;
    int cnt = g_cnto[bq];
    const uint2* lrow = g_listo + (size_t)bq*NN;
    for (int i = tid; i < cnt; i += T) sl[i] = lrow[i];
    for (int i = tid; i < KBINS+1; i += T) sb[i] = g_boffo[bq*49 + i];
    for (int i = tid; i < NN*2; i += T) sbf[i] = box_feats[b*NN*2 + i];
    __syncthreads();
    if (tid < 96) {
        int k = tid >> 1, v = tid & 1;
        float acc = 0.f;
        int e1 = sb[k+1];
        for (int e = sb[k]; e < e1; ++e) {
            uint2 pk = sl[e];
            acc += __uint_as_float(pk.x) * sbf[(pk.y & 0xffff)*2 + v];
        }
        sXo[tid] = acc;
    }
    __syncthreads();
    if (tid < 16) {
        float x = 0.f, y = 0.f;
        #pragma unroll 8
        for (int k = 0; k < 96; ++k) {
            float xv = sXo[k];
            x += xv * KSo[k*32 + 2*tid];
            y += xv * KSo[k*32 + 2*tid + 1];
        }
        float mag = x*x + y*y + 1e-6f;
        float sc = fmaxf(mag - 0.2f, 0.f) / mag;
        g_feats[bq*96 + 2*tid]   = x*sc;
        g_feats[bq*96 + 2*tid+1] = y*sc;
    }
}

__global__ void k_bin1(const float* __restrict__ feats, const float* __restrict__ boxf,
                       const float* __restrict__ KSo)
{
    if (blockIdx.y == 0) bin_body<40, 1984, 12>(feats);
    else                 bino_body(boxf, KSo);
}

// ---- fp16 tensor-core GEMM: mma.m16n8k16, BM=64, plain split-K partials ----
__global__ void k_gemm_mma(const __half* __restrict__ X, const __half* __restrict__ Wt, int inner)
{
    __shared__ __half As[64][40];
    __shared__ __half Bs[64][40];
    int tid = threadIdx.x, lane = tid & 31, warp = tid >> 5;
    int row0 = blockIdx.x * 64;
    int ntiles = inner / 32;
    int per = (ntiles + NSPLIT - 1) / NSPLIT;
    int t0 = blockIdx.y * per;
    int t1 = min(ntiles, t0 + per);
    int g = lane >> 2, q = lane & 3;

    float acc[8][4];
    #pragma unroll
    for (int b = 0; b < 8; ++b)
        #pragma unroll
        for (int c = 0; c < 4; ++c) acc[b][c] = 0.f;

    for (int t = t0; t < t1; ++t) {
        int kk = t*32;
        #pragma unroll
        for (int r = 0; r < 2; ++r) {
            int idx = tid + r*128;
            int m = idx >> 2, c8 = (idx & 3)*8;
            uint4 v = *(const uint4*)&X[(size_t)(row0+m)*inner + kk + c8];
            *(uint4*)&As[m][c8] = v;
        }
        #pragma unroll
        for (int r = 0; r < 2; ++r) {
            int idx = tid + r*128;
            int n = idx >> 2, c8 = (idx & 3)*8;
            uint4 v = *(const uint4*)&Wt[(size_t)n*inner + kk + c8];
            *(uint4*)&Bs[n][c8] = v;
        }
        __syncthreads();
        #pragma unroll
        for (int k16 = 0; k16 < 2; ++k16) {
            int kb = k16*16;
            int mr = warp*16 + g;
            uint32_t a0 = *(const uint32_t*)&As[mr][kb + 2*q];
            uint32_t a1 = *(const uint32_t*)&As[mr+8][kb + 2*q];
            uint32_t a2 = *(const uint32_t*)&As[mr][kb + 2*q + 8];
            uint32_t a3 = *(const uint32_t*)&As[mr+8][kb + 2*q + 8];
            #pragma unroll
            for (int nt = 0; nt < 8; ++nt) {
                int nc = nt*8 + g;
                uint32_t b0 = *(const uint32_t*)&Bs[nc][kb + 2*q];
                uint32_t b1 = *(const uint32_t*)&Bs[nc][kb + 2*q + 8];
                asm volatile(
                    "mma.sync.aligned.m16n8k16.row.col.f32.f16.f16.f32 "
                    "{%0,%1,%2,%3}, {%4,%5,%6,%7}, {%8,%9}, {%0,%1,%2,%3};"
                    : "+f"(acc[nt][0]), "+f"(acc[nt][1]),
                      "+f"(acc[nt][2]), "+f"(acc[nt][3])
                    : "r"(a0), "r"(a1), "r"(a2), "r"(a3),
                      "r"(b0), "r"(b1));
            }
        }
        __syncthreads();
    }
    float* pb = g_part + ((size_t)blockIdx.y*BQ + row0)*64;
    int r0 = warp*16 + g;
    #pragma unroll
    for (int nt = 0; nt < 8; ++nt) {
        int c = nt*8 + q*2;
        *(float2*)&pb[(size_t)r0*64 + c]     = make_float2(acc[nt][0], acc[nt][1]);
        *(float2*)&pb[(size_t)(r0+8)*64 + c] = make_float2(acc[nt][2], acc[nt][3]);
    }
}

// stage-1 fluid finish: reduce partials + nonlin -> feats cols 32..95 (ld 96)
__global__ void k_finnl_s1()
{
    int idx = blockIdx.x*blockDim.x + threadIdx.x;
    if (idx >= BQ*32) return;
    int row = idx >> 5, c = idx & 31;
    float x = 0.f, y = 0.f;
    #pragma unroll
    for (int s = 0; s < NSPLIT; ++s) {
        const float* p = g_part + ((size_t)s*BQ + row)*64 + c*2;
        x += p[0]; y += p[1];
    }
    float mag = x*x + y*y + 1e-6f;
    float sc = fmaxf(mag - 0.2f, 0.f) / mag;
    g_feats[row*96 + 32 + c*2]   = x*sc;
    g_feats[row*96 + 32 + c*2+1] = y*sc;
}

// layer finish: reduce partials + residual + nonlin (ld 64)
__global__ void k_finnl(float* __restrict__ out, const float* __restrict__ res)
{
    int idx = blockIdx.x*blockDim.x + threadIdx.x;
    if (idx >= BQ*32) return;
    int row = idx >> 5, c = idx & 31;
    float x = 0.f, y = 0.f;
    #pragma unroll
    for (int s = 0; s < NSPLIT; ++s) {
        const float* p = g_part + ((size_t)s*BQ + row)*64 + c*2;
        x += p[0]; y += p[1];
    }
    if (res) { x += res[row*64 + c*2]; y += res[row*64 + c*2+1]; }
    out[row*64 + c*2] = x; out[row*64 + c*2+1] = y;
    float mag = x*x + y*y + 1e-6f;
    float sc = fmaxf(mag - 0.2f, 0.f) / mag;
    g_feats[row*64 + c*2]   = x*sc;
    g_feats[row*64 + c*2+1] = y*sc;
}

// layer 4 GEMV (fp32 weights, fp16 X) fused with final correction
__global__ void k_gemv_final(const __half* __restrict__ X, const float* __restrict__ Wm,
                             int inner, const float* __restrict__ p0,
                             float* __restrict__ dout, int half)
{
    __shared__ float Wsh[3136*2];
    int tid = threadIdx.x;
    for (int i = tid; i < inner*2; i += blockDim.x) Wsh[i] = Wm[i];
    __syncthreads();
    int warp = tid >> 5, lane = tid & 31;
    int row = blockIdx.x*8 + warp;
    const __half* xr = X + (size_t)row*inner;
    float a0 = 0.f, a1 = 0.f;
    for (int k = lane; k < inner; k += 32) {
        float x = __half2float(xr[k]);
        a0 += x*Wsh[k*2];
        a1 += x*Wsh[k*2+1];
    }
    #pragma unroll
    for (int o = 16; o; o >>= 1) {
        a0 += __shfl_down_sync(0xffffffffu, a0, o);
        a1 += __shfl_down_sync(0xffffffffu, a1, o);
    }
    if (lane == 0) {
        float px = g_p1[row*2]   + a0*(1.0f/128.0f);
        float py = g_p1[row*2+1] + a1*(1.0f/128.0f);
        dout[row*2]   = px;
        dout[row*2+1] = py;
        dout[half + row*2]   = (px - p0[row*2])  *10.0f;
        dout[half + row*2+1] = (py - p0[row*2+1])*10.0f;
    }
}

// ---------------- host driver ----------------
extern "C" void kernel_launch(void* const* d_in, const int* in_sizes, int n_in,
                              void* d_out, int out_size)
{
    const float* v0_enc = (const float*)d_in[1];
    const float* p0     = (const float*)d_in[2];
    const float* v0     = (const float*)d_in[3];
    const float* a      = (const float*)d_in[4];
    const float* other  = (const float*)d_in[5];
    const float* box    = (const float*)d_in[6];
    const float* boxf   = (const float*)d_in[7];
    const float* fmask  = (const float*)d_in[8];
    const float* bmask  = (const float*)d_in[9];
    float* dout = (float*)d_out;
    int half = out_size / 2;

    __half *Xh, *KSh; float *KSf, *outA, *outB, *feats;
    cudaGetSymbolAddress((void**)&Xh,    g_Xh);
    cudaGetSymbolAddress((void**)&KSh,   g_KSh);
    cudaGetSymbolAddress((void**)&KSf,   g_KSf);
    cudaGetSymbolAddress((void**)&outA,  g_outA);
    cudaGetSymbolAddress((void**)&outB,  g_outB);
    cudaGetSymbolAddress((void**)&feats, g_feats);

    SteerArgs sa;
    sa.Wc[0] = (const float*)d_in[10]; sa.Ad[0] = (const float*)d_in[12]; sa.Bd[0] = (const float*)d_in[13];
    sa.Wc[1] = (const float*)d_in[11]; sa.Ad[1] = nullptr;                sa.Bd[1] = nullptr;
    sa.Wc[2] = (const float*)d_in[14]; sa.Ad[2] = (const float*)d_in[15]; sa.Bd[2] = (const float*)d_in[16];
    sa.Wc[3] = (const float*)d_in[17]; sa.Ad[3] = (const float*)d_in[18]; sa.Bd[3] = (const float*)d_in[19];
    sa.Wc[4] = (const float*)d_in[20]; sa.Ad[4] = (const float*)d_in[21]; sa.Bd[4] = (const float*)d_in[22];
    sa.Wc[5] = (const float*)d_in[23]; sa.Ad[5] = (const float*)d_in[24]; sa.Bd[5] = (const float*)d_in[25];

    dim3 gg(BQ/64, NSPLIT);   // 32 x 8 = 256 CTAs

    // 1. integrate + 20-ch fluid feats
    k_prep<<<(BQ+127)/128, 128>>>(p0, v0, a, other, v0_enc);
    // 2. fused geometry + compaction + bin sort (fluid & obstacle)
    k_compact2<<<dim3(BQ/8, 2), 256>>>(box, fmask, bmask);
    // 3. steered matrices (quarter-threaded, fp16 TC segments)
    k_steer_all<<<(SQ5+255)/256, 256>>>(sa);
    // 4. stage-1 binning: fluid bin40 + obstacle bin+conv -> feats cols 0..31
    k_bin1<<<dim3(BQ, 2), 240>>>(feats, boxf, KSf+F1B);
    // 5. stage-1 GEMM + fluid finish -> feats cols 32..95
    k_gemm_mma<<<gg, 128>>>(Xh, KSh+H1A, 1984);
    k_finnl_s1<<<(BQ*32+255)/256, 256>>>();
    // 6. layer 1: 48 -> 32
    k_bin<96,4704,6><<<BQ, 288>>>(feats);
    k_gemm_mma<<<gg, 128>>>(Xh, KSh+HL1, 4704);
    k_finnl<<<(BQ*32+255)/256, 256>>>(outB, nullptr);
    // 7. layer 2: 32 -> 32, residual
    k_bin<64,3136,8><<<BQ, 256>>>(feats);
    k_gemm_mma<<<gg, 128>>>(Xh, KSh+HL2, 3136);
    k_finnl<<<(BQ*32+255)/256, 256>>>(outA, outB);
    // 8. layer 3: 32 -> 32, residual
    k_bin<64,3136,8><<<BQ, 256>>>(feats);
    k_gemm_mma<<<gg, 128>>>(Xh, KSh+HL3, 3136);
    k_finnl<<<(BQ*32+255)/256, 256>>>(outB, outA);
    // 9. layer 4: 32 -> 1 (GEMV fused with final correction)
    k_bin<64,3136,8><<<BQ, 256>>>(feats);
    k_gemv_final<<<BQ/8, 256>>>(Xh, KSf+FL4, 3136, p0, dout, half);
}

// round 16
// speedup vs baseline: 1.1922x; 1.0205x over previous
#include <cuda_runtime.h>
#include <cuda_fp16.h>
#include <math.h>
#include <stdint.h>

#define BB 4
#define NN 512
#define BQ 2048
#define KBINS 48
#define PI_F 3.14159265358979f
#define NSPLIT 8

typedef unsigned long long ull;

// ---------------- device scratch ----------------
__device__ __align__(16) __half g_Xh[BQ * 4704];
__device__ __align__(16) uint2 g_list [BQ * NN];
__device__ int   g_cnt [BQ];
__device__ int   g_boff[BQ * 49];
__device__ __align__(16) uint2 g_listo[BQ * NN];
__device__ int   g_cnto[BQ];
__device__ int   g_boffo[BQ * 49];
__device__ __align__(16) __half g_KSh[829440];   // TC weight segments (half)
__device__ __align__(16) float  g_KSf[9344];     // obstacle (96x32) + gemv (3136x2)
__device__ __align__(16) float g_part[NSPLIT * BQ * 64];
__device__ __align__(16) float g_outA[BQ * 96];
__device__ __align__(16) float g_outB[BQ * 96];
__device__ __align__(16) float g_feats[BQ * 96];
__device__ float g_p1[BQ * 2];

// half-KS segment offsets (in halves)
#define H1A 0          // 64 x 1984
#define HL1 126976     // 64 x 4704
#define HL2 428032     // 64 x 3136
#define HL3 628736     // 64 x 3136
// float-KS offsets
#define F1B 0          // 96 x 32 row-major (obstacle)
#define FL4 3072       // 3136 x 2 row-major (layer 4)

// quarter-thread prefix for k_steer_all
#define SQ0 31744
#define SQ1 107008
#define SQ2 157184
#define SQ3 207360
#define SQ4 210432
#define SQ5 216704

// ---------------- kernels ----------------

__global__ void k_prep(const float* __restrict__ p0, const float* __restrict__ v0,
                       const float* __restrict__ a, const float* __restrict__ other,
                       const float* __restrict__ v0enc)
{
    int i = blockIdx.x*blockDim.x + threadIdx.x;
    if (i >= BQ) return;
    float v0x = v0[i*2], v0y = v0[i*2+1];
    float v1x = v0x + 0.1f*a[i*2], v1y = v0y + 0.1f*a[i*2+1];
    g_p1[i*2]   = p0[i*2]   + 0.05f*(v0x+v1x);
    g_p1[i*2+1] = p0[i*2+1] + 0.05f*(v0y+v1y);
    float* f = g_feats + i*40;
    f[0]=v1x; f[1]=v1y;
    #pragma unroll
    for (int c=0;c<3;c++){ f[2+c*2]=other[(i*3+c)*2]; f[3+c*2]=other[(i*3+c)*2+1]; }
    #pragma unroll
    for (int c=0;c<16;c++){ f[8+c*2]=v0enc[(i*16+c)*2]; f[9+c*2]=v0enc[(i*16+c)*2+1]; }
}

// geometry + compaction + stable counting sort by bin. One warp per query.
__global__ void k_compact2(const float* __restrict__ box,
                           const float* __restrict__ fmask, const float* __restrict__ bmask)
{
    __shared__ uint2 s_tmp[8][NN];
    __shared__ int s_cnt[8][KBINS];
    __shared__ int s_off[8][KBINS+1];
    __shared__ int s_run[8][KBINS];
    int wIn = threadIdx.x >> 5;
    int lane = threadIdx.x & 31;
    int warp = blockIdx.x*8 + wIn;
    int b = warp >> 9, q = warp & 511;
    bool fluid = (blockIdx.y == 0);
    const float* src = fluid ? g_p1 : box;
    const float* mrow = (fluid ? fmask : bmask) + (size_t)warp*NN;
    uint2* list = fluid ? g_list : g_listo;
    int* cnt  = fluid ? g_cnt : g_cnto;
    int* boff = fluid ? g_boff : g_boffo;
    float qx = g_p1[(b*NN+q)*2], qy = g_p1[(b*NN+q)*2+1];
    for (int i = lane; i < KBINS; i += 32) { s_cnt[wIn][i] = 0; s_run[wIn][i] = 0; }
    __syncwarp();
    int base = 0;
    for (int c = 0; c < NN; c += 32) {
        int s = c + lane;
        float rx = src[(b*NN+s)*2]   - qx;
        float ry = src[(b*NN+s)*2+1] - qy;
        float d2 = rx*rx + ry*ry;
        float m = mrow[s];
        float win = 1.0f - d2*(1.0f/1600.0f);
        bool on = (win > 0.f) && (m != 0.f);
        float wv = 0.f; int kidx = 0;
        if (on) {
            wv = win*win*win*m;
            float dist = sqrtf(d2 + 1e-9f);
            int rb = (int)(dist*(3.0f/40.0f)); if (rb > 2) rb = 2;
            int tb = ((int)floorf((atan2f(ry,rx) + PI_F)*(16.0f/(2.0f*PI_F)))) & 15;
            kidx = rb*16 + tb;
        }
        unsigned mk = __ballot_sync(0xffffffffu, on);
        if (on) {
            int pos = base + __popc(mk & ((1u<<lane)-1u));
            s_tmp[wIn][pos] = make_uint2(__float_as_uint(wv), (unsigned)((kidx<<16) | s));
        }
        base += __popc(mk);
    }
    __syncwarp();
    for (int e = lane; e < base; e += 32)
        atomicAdd(&s_cnt[wIn][s_tmp[wIn][e].y >> 16], 1);
    __syncwarp();
    if (lane == 0) {
        int acc = 0;
        #pragma unroll
        for (int k = 0; k < KBINS; ++k) { s_off[wIn][k] = acc; acc += s_cnt[wIn][k]; }
        s_off[wIn][KBINS] = acc;
    }
    __syncwarp();
    uint2* lrow = list + (size_t)warp*NN;
    for (int c = 0; c < base; c += 32) {
        int e = c + lane;
        bool valid = e < base;
        unsigned msk = __ballot_sync(0xffffffffu, valid);
        int bin = 0, rank = 0, gcnt = 0; bool lead = false; uint2 pk;
        if (valid) {
            pk = s_tmp[wIn][e];
            bin = pk.y >> 16;
            unsigned grp = __match_any_sync(msk, bin);
            rank = __popc(grp & ((1u<<lane)-1u));
            lead = ((__ffs(grp)-1) == lane);
            gcnt = __popc(grp);
        }
        int runv = valid ? s_run[wIn][bin] : 0;
        __syncwarp();
        if (valid) {
            lrow[s_off[wIn][bin] + runv + rank] = pk;
            if (lead) s_run[wIn][bin] = runv + gcnt;
        }
        __syncwarp();
    }
    for (int k = lane; k < KBINS+1; k += 32) boff[warp*49 + k] = s_off[wIn][k];
    if (lane == 0) cnt[warp] = base;
}

// ---- steered-kernel assembly ----
struct SteerArgs { const float* Wc[6]; const float* Ad[6]; const float* Bd[6]; };

template<int O, int I, int COLS, int DOFF>
__device__ __forceinline__ float steer_val_rm(int idx, const float* __restrict__ Wc,
                                              const float* __restrict__ Ad,
                                              const float* __restrict__ Bd,
                                              const float* tc, const float* ts)
{
    constexpr int IV = 2*I;
    int row = idx / COLS, col = idx - (idx/COLS)*COLS;
    float val = 0.f;
    if (row < KBINS*IV) {
        if (col < 2*O) {
            int k = row / IV, iv = row - (row/IV)*IV, i = iv>>1, v = iv&1;
            int o = col>>1, u = col&1;
            float c = tc[k & 15], s = ts[k & 15];
            float R[2][2] = {{c,-s},{s,c}};
            const float* Wb = Wc + (((long long)k*O + o)*I + i)*4;
            val = R[u][0]*(Wb[0]*R[v][0] + Wb[1]*R[v][1])
                + R[u][1]*(Wb[2]*R[v][0] + Wb[3]*R[v][1]);
        }
    } else if (row < KBINS*IV + IV) {
        if (DOFF >= 0 && col >= DOFF && col < DOFF + 2*O) {
            int iv = row - KBINS*IV, i = iv>>1, v = iv&1;
            int oc = col - DOFF, o = oc>>1, u = oc&1;
            if (u == v) val = Ad[o*I+i];
            else        val = (u==0) ? -Bd[o*I+i] : Bd[o*I+i];
        }
    }
    return val;
}

template<int O, int I, int K, bool SEG0>
__device__ __forceinline__ void steer_quarter(int qi, int off,
                                              const float* __restrict__ Wc,
                                              const float* __restrict__ Ad,
                                              const float* __restrict__ Bd,
                                              const float* tc, const float* ts)
{
    constexpr int IV = 2*I;
    constexpr int halfK = K/2;
    int op = qi / halfK, rk = qi - op*halfK;
    int row0 = rk*2;
    float v00=0.f, v01=0.f, v10=0.f, v11=0.f;
    if (row0 < KBINS*IV) {
        if (!SEG0 || op < O) {
            int o = op;
            int k = row0 / IV;
            int i = (row0 - k*IV) >> 1;
            float c = tc[k & 15], s = ts[k & 15];
            const float* Wb = Wc + (((long long)k*O + o)*I + i)*4;
            float w0=Wb[0], w1=Wb[1], w2=Wb[2], w3=Wb[3];
            float ta0 = w0*c + w1*(-s), tb0 = w2*c + w3*(-s);
            float ta1 = w0*s + w1*c,    tb1 = w2*s + w3*c;
            v00 = c*ta0 + (-s)*tb0;  v01 = c*ta1 + (-s)*tb1;
            v10 = s*ta0 + c*tb0;     v11 = s*ta1 + c*tb1;
        }
    } else if (row0 < KBINS*IV + IV) {
        if (!SEG0 || op >= O) {
            int o = SEG0 ? (op - O) : op;
            int i = (row0 - KBINS*IV) >> 1;
            float A = Ad[o*I+i], Bv = Bd[o*I+i];
            v00 = A; v01 = -Bv; v10 = Bv; v11 = A;
        }
    }
    __half* p0 = g_KSh + off + (size_t)(2*op)*K + row0;
    *(__half2*)p0       = __floats2half2_rn(v00, v01);
    *(__half2*)(p0 + K) = __floats2half2_rn(v10, v11);
}

__global__ void k_steer_all(SteerArgs args)
{
    __shared__ float tc[16], ts[16];
    if (threadIdx.x < 16) {
        float th = (threadIdx.x + 0.5f)*(2.0f*PI_F/16.0f) - PI_F;
        tc[threadIdx.x] = cosf(th);
        ts[threadIdx.x] = sinf(th);
    }
    __syncthreads();
    int gidx = blockIdx.x*blockDim.x + threadIdx.x;
    if (gidx >= SQ5) return;
    if (gidx < SQ0) {
        steer_quarter<16,20,1984,true>(gidx, H1A, args.Wc[0], args.Ad[0], args.Bd[0], tc, ts);
    } else if (gidx < SQ1) {
        steer_quarter<32,48,4704,false>(gidx-SQ0, HL1, args.Wc[2], args.Ad[2], args.Bd[2], tc, ts);
    } else if (gidx < SQ2) {
        steer_quarter<32,32,3136,false>(gidx-SQ1, HL2, args.Wc[3], args.Ad[3], args.Bd[3], tc, ts);
    } else if (gidx < SQ3) {
        steer_quarter<32,32,3136,false>(gidx-SQ2, HL3, args.Wc[4], args.Ad[4], args.Bd[4], tc, ts);
    } else if (gidx < SQ4) {
        int idx = gidx - SQ3;
        g_KSf[F1B + idx] = steer_val_rm<16,1,32,-1>(idx, args.Wc[1], 0, 0, tc, ts);
    } else {
        int idx = gidx - SQ4;
        g_KSf[FL4 + idx] = steer_val_rm<1,32,2,0>(idx, args.Wc[5], args.Ad[5], args.Bd[5], tc, ts);
    }
}

// ---- fluid binning body: dual-accumulator unroll, fp16 output ----
template<int IV, int LD, int NG>
__device__ __forceinline__ void bin_body(const float* __restrict__ feats)
{
    constexpr int HV = IV/2;
    constexpr int T = HV*NG;
    __shared__ uint2 sl[NN];
    __shared__ int sb[KBINS+1];
    int bq = blockIdx.x, tid = threadIdx.x, b = bq >> 9;
    int cnt = g_cnt[bq];
    const uint2* lrow = g_list + (size_t)bq*NN;
    for (int i = tid; i < cnt; i += T) sl[i] = lrow[i];
    for (int i = tid; i < KBINS+1; i += T) sb[i] = g_boff[bq*49 + i];
    __syncthreads();
    int col = tid % HV, grp = tid / HV;
    const float2* fb = (const float2*)feats + (size_t)(b*NN)*HV + col;
    __half* xr = g_Xh + (size_t)bq*LD;
    for (int k = grp; k < KBINS; k += NG) {
        int e = sb[k], e1 = sb[k+1];
        float2 a0 = make_float2(0.f, 0.f), a1 = make_float2(0.f, 0.f);
        for (; e + 2 <= e1; e += 2) {
            uint2 p0 = sl[e], p1 = sl[e+1];
            float2 f0 = fb[(size_t)(p0.y & 0xffff)*HV];
            float2 f1 = fb[(size_t)(p1.y & 0xffff)*HV];
            float w0 = __uint_as_float(p0.x), w1 = __uint_as_float(p1.x);
            a0.x += w0*f0.x; a0.y += w0*f0.y;
            a1.x += w1*f1.x; a1.y += w1*f1.y;
        }
        if (e < e1) {
            uint2 p0 = sl[e];
            float2 f0 = fb[(size_t)(p0.y & 0xffff)*HV];
            float w0 = __uint_as_float(p0.x);
            a0.x += w0*f0.x; a0.y += w0*f0.y;
        }
        *(__half2*)&xr[k*IV + 2*col] = __floats2half2_rn(a0.x + a1.x, a0.y + a1.y);
    }
    for (int i = tid; i < IV; i += T)
        xr[KBINS*IV + i] = __float2half_rn(feats[(size_t)bq*IV + i]);
    for (int i = 49*IV + tid; i < LD; i += T) xr[i] = __float2half_rn(0.f);
}

template<int IV, int LD, int NG>
__global__ void k_bin(const float* __restrict__ feats)
{
    bin_body<IV, LD, NG>(feats);
}

// obstacle binning + obstacle conv fused: writes g_feats cols 0..31 directly
__device__ __forceinline__ void bino_body(const float* __restrict__ box_feats,
                                          const float* __restrict__ KSo)
{
    __shared__ uint2 sl[NN];
    __shared__ float sbf[NN*2];
    __shared__ int sb[KBINS+1];
    __shared__ float sXo[96];
    int bq = blockIdx.x, tid = threadIdx.x, b = bq >> 9;
    int T = blockDim.x;
    int cnt = g_cnto[bq];
    const uint2* lrow = g_listo + (size_t)bq*NN;
    for (int i = tid; i < cnt; i += T) sl[i] = lrow[i];
    for (int i = tid; i < KBINS+1; i += T) sb[i] = g_boffo[bq*49 + i];
    for (int i = tid; i < NN*2; i += T) sbf[i] = box_feats[b*NN*2 + i];
    __syncthreads();
    if (tid < 96) {
        int k = tid >> 1, v = tid & 1;
        float acc = 0.f;
        int e1 = sb[k+1];
        for (int e = sb[k]; e < e1; ++e) {
            uint2 pk = sl[e];
            acc += __uint_as_float(pk.x) * sbf[(pk.y & 0xffff)*2 + v];
        }
        sXo[tid] = acc;
    }
    __syncthreads();
    if (tid < 16) {
        float x = 0.f, y = 0.f;
        #pragma unroll 8
        for (int k = 0; k < 96; ++k) {
            float xv = sXo[k];
            x += xv * KSo[k*32 + 2*tid];
            y += xv * KSo[k*32 + 2*tid + 1];
        }
        float mag = x*x + y*y + 1e-6f;
        float sc = fmaxf(mag - 0.2f, 0.f) / mag;
        g_feats[bq*96 + 2*tid]   = x*sc;
        g_feats[bq*96 + 2*tid+1] = y*sc;
    }
}

__global__ void k_bin1(const float* __restrict__ feats, const float* __restrict__ boxf,
                       const float* __restrict__ KSo)
{
    if (blockIdx.y == 0) bin_body<40, 1984, 12>(feats);
    else                 bino_body(boxf, KSo);
}

// ---- fp16 tensor-core GEMM: mma.m16n8k16, BM=64, plain split-K partials ----
__global__ void k_gemm_mma(const __half* __restrict__ X, const __half* __restrict__ Wt, int inner)
{
    __shared__ __half As[64][40];
    __shared__ __half Bs[64][40];
    int tid = threadIdx.x, lane = tid & 31, warp = tid >> 5;
    int row0 = blockIdx.x * 64;
    int ntiles = inner / 32;
    int per = (ntiles + NSPLIT - 1) / NSPLIT;
    int t0 = blockIdx.y * per;
    int t1 = min(ntiles, t0 + per);
    int g = lane >> 2, q = lane & 3;

    float acc[8][4];
    #pragma unroll
    for (int b = 0; b < 8; ++b)
        #pragma unroll
        for (int c = 0; c < 4; ++c) acc[b][c] = 0.f;

    for (int t = t0; t < t1; ++t) {
        int kk = t*32;
        #pragma unroll
        for (int r = 0; r < 2; ++r) {
            int idx = tid + r*128;
            int m = idx >> 2, c8 = (idx & 3)*8;
            uint4 v = *(const uint4*)&X[(size_t)(row0+m)*inner + kk + c8];
            *(uint4*)&As[m][c8] = v;
        }
        #pragma unroll
        for (int r = 0; r < 2; ++r) {
            int idx = tid + r*128;
            int n = idx >> 2, c8 = (idx & 3)*8;
            uint4 v = *(const uint4*)&Wt[(size_t)n*inner + kk + c8];
            *(uint4*)&Bs[n][c8] = v;
        }
        __syncthreads();
        #pragma unroll
        for (int k16 = 0; k16 < 2; ++k16) {
            int kb = k16*16;
            int mr = warp*16 + g;
            uint32_t a0 = *(const uint32_t*)&As[mr][kb + 2*q];
            uint32_t a1 = *(const uint32_t*)&As[mr+8][kb + 2*q];
            uint32_t a2 = *(const uint32_t*)&As[mr][kb + 2*q + 8];
            uint32_t a3 = *(const uint32_t*)&As[mr+8][kb + 2*q + 8];
            #pragma unroll
            for (int nt = 0; nt < 8; ++nt) {
                int nc = nt*8 + g;
                uint32_t b0 = *(const uint32_t*)&Bs[nc][kb + 2*q];
                uint32_t b1 = *(const uint32_t*)&Bs[nc][kb + 2*q + 8];
                asm volatile(
                    "mma.sync.aligned.m16n8k16.row.col.f32.f16.f16.f32 "
                    "{%0,%1,%2,%3}, {%4,%5,%6,%7}, {%8,%9}, {%0,%1,%2,%3};"
                    : "+f"(acc[nt][0]), "+f"(acc[nt][1]),
                      "+f"(acc[nt][2]), "+f"(acc[nt][3])
                    : "r"(a0), "r"(a1), "r"(a2), "r"(a3),
                      "r"(b0), "r"(b1));
            }
        }
        __syncthreads();
    }
    float* pb = g_part + ((size_t)blockIdx.y*BQ + row0)*64;
    int r0 = warp*16 + g;
    #pragma unroll
    for (int nt = 0; nt < 8; ++nt) {
        int c = nt*8 + q*2;
        *(float2*)&pb[(size_t)r0*64 + c]     = make_float2(acc[nt][0], acc[nt][1]);
        *(float2*)&pb[(size_t)(r0+8)*64 + c] = make_float2(acc[nt][2], acc[nt][3]);
    }
}

// stage-1 fluid finish: reduce partials + nonlin -> feats cols 32..95 (ld 96)
__global__ void k_finnl_s1()
{
    int idx = blockIdx.x*blockDim.x + threadIdx.x;
    if (idx >= BQ*32) return;
    int row = idx >> 5, c = idx & 31;
    float x = 0.f, y = 0.f;
    #pragma unroll
    for (int s = 0; s < NSPLIT; ++s) {
        const float* p = g_part + ((size_t)s*BQ + row)*64 + c*2;
        x += p[0]; y += p[1];
    }
    float mag = x*x + y*y + 1e-6f;
    float sc = fmaxf(mag - 0.2f, 0.f) / mag;
    g_feats[row*96 + 32 + c*2]   = x*sc;
    g_feats[row*96 + 32 + c*2+1] = y*sc;
}

// layer finish: reduce partials + residual + nonlin (ld 64)
__global__ void k_finnl(float* __restrict__ out, const float* __restrict__ res)
{
    int idx = blockIdx.x*blockDim.x + threadIdx.x;
    if (idx >= BQ*32) return;
    int row = idx >> 5, c = idx & 31;
    float x = 0.f, y = 0.f;
    #pragma unroll
    for (int s = 0; s < NSPLIT; ++s) {
        const float* p = g_part + ((size_t)s*BQ + row)*64 + c*2;
        x += p[0]; y += p[1];
    }
    if (res) { x += res[row*64 + c*2]; y += res[row*64 + c*2+1]; }
    out[row*64 + c*2] = x; out[row*64 + c*2+1] = y;
    float mag = x*x + y*y + 1e-6f;
    float sc = fmaxf(mag - 0.2f, 0.f) / mag;
    g_feats[row*64 + c*2]   = x*sc;
    g_feats[row*64 + c*2+1] = y*sc;
}

// ---- layer 4 fused: bin + 2-col conv + dense + final correction ----
// One warp per query; lane owns channel pair (2l, 2l+1); entries looped directly.
__global__ void k_last(const float* __restrict__ Wm, const float* __restrict__ p0,
                       float* __restrict__ dout, int half)
{
    __shared__ float Wsh[3136*2];
    int tid = threadIdx.x;
    for (int i = tid; i < 3136*2; i += 256) Wsh[i] = Wm[i];
    __syncthreads();
    int warp = tid >> 5, lane = tid & 31;
    int bq = blockIdx.x*8 + warp;
    int b = bq >> 9;
    int cnt = g_cnt[bq];
    const uint2* lrow = g_list + (size_t)bq*NN;
    const float* fbat = g_feats + (size_t)(b*NN)*64 + 2*lane;
    float a0 = 0.f, a1 = 0.f, b0 = 0.f, b1 = 0.f;
    int e = 0;
    for (; e + 2 <= cnt; e += 2) {
        uint2 pA = lrow[e], pB = lrow[e+1];
        float wA = __uint_as_float(pA.x), wB = __uint_as_float(pB.x);
        int sA = pA.y & 0xffff, kA = pA.y >> 16;
        int sB = pB.y & 0xffff, kB = pB.y >> 16;
        float2 fA = *(const float2*)&fbat[(size_t)sA*64];
        float2 fB = *(const float2*)&fbat[(size_t)sB*64];
        float4 wrA = *(const float4*)&Wsh[(kA*64 + 2*lane)*2];
        float4 wrB = *(const float4*)&Wsh[(kB*64 + 2*lane)*2];
        a0 += wA * (fA.x*wrA.x + fA.y*wrA.z);
        a1 += wA * (fA.x*wrA.y + fA.y*wrA.w);
        b0 += wB * (fB.x*wrB.x + fB.y*wrB.z);
        b1 += wB * (fB.x*wrB.y + fB.y*wrB.w);
    }
    if (e < cnt) {
        uint2 pA = lrow[e];
        float wA = __uint_as_float(pA.x);
        int sA = pA.y & 0xffff, kA = pA.y >> 16;
        float2 fA = *(const float2*)&fbat[(size_t)sA*64];
        float4 wrA = *(const float4*)&Wsh[(kA*64 + 2*lane)*2];
        a0 += wA * (fA.x*wrA.x + fA.y*wrA.z);
        a1 += wA * (fA.x*wrA.y + fA.y*wrA.w);
    }
    a0 += b0; a1 += b1;
    {   // dense row block (weight rows 48*64 ..)
        float2 f = *(const float2*)&g_feats[(size_t)bq*64 + 2*lane];
        float4 wr = *(const float4*)&Wsh[(KBINS*64 + 2*lane)*2];
        a0 += f.x*wr.x + f.y*wr.z;
        a1 += f.x*wr.y + f.y*wr.w;
    }
    #pragma unroll
    for (int o = 16; o; o >>= 1) {
        a0 += __shfl_down_sync(0xffffffffu, a0, o);
        a1 += __shfl_down_sync(0xffffffffu, a1, o);
    }
    if (lane == 0) {
        float px = g_p1[bq*2]   + a0*(1.0f/128.0f);
        float py = g_p1[bq*2+1] + a1*(1.0f/128.0f);
        dout[bq*2]   = px;
        dout[bq*2+1] = py;
        dout[half + bq*2]   = (px - p0[bq*2])  *10.0f;
        dout[half + bq*2+1] = (py - p0[bq*2+1])*10.0f;
    }
}

// ---------------- host driver ----------------
extern "C" void kernel_launch(void* const* d_in, const int* in_sizes, int n_in,
                              void* d_out, int out_size)
{
    const float* v0_enc = (const float*)d_in[1];
    const float* p0     = (const float*)d_in[2];
    const float* v0     = (const float*)d_in[3];
    const float* a      = (const float*)d_in[4];
    const float* other  = (const float*)d_in[5];
    const float* box    = (const float*)d_in[6];
    const float* boxf   = (const float*)d_in[7];
    const float* fmask  = (const float*)d_in[8];
    const float* bmask  = (const float*)d_in[9];
    float* dout = (float*)d_out;
    int half = out_size / 2;

    __half *Xh, *KSh; float *KSf, *outA, *outB, *feats;
    cudaGetSymbolAddress((void**)&Xh,    g_Xh);
    cudaGetSymbolAddress((void**)&KSh,   g_KSh);
    cudaGetSymbolAddress((void**)&KSf,   g_KSf);
    cudaGetSymbolAddress((void**)&outA,  g_outA);
    cudaGetSymbolAddress((void**)&outB,  g_outB);
    cudaGetSymbolAddress((void**)&feats, g_feats);

    SteerArgs sa;
    sa.Wc[0] = (const float*)d_in[10]; sa.Ad[0] = (const float*)d_in[12]; sa.Bd[0] = (const float*)d_in[13];
    sa.Wc[1] = (const float*)d_in[11]; sa.Ad[1] = nullptr;                sa.Bd[1] = nullptr;
    sa.Wc[2] = (const float*)d_in[14]; sa.Ad[2] = (const float*)d_in[15]; sa.Bd[2] = (const float*)d_in[16];
    sa.Wc[3] = (const float*)d_in[17]; sa.Ad[3] = (const float*)d_in[18]; sa.Bd[3] = (const float*)d_in[19];
    sa.Wc[4] = (const float*)d_in[20]; sa.Ad[4] = (const float*)d_in[21]; sa.Bd[4] = (const float*)d_in[22];
    sa.Wc[5] = (const float*)d_in[23]; sa.Ad[5] = (const float*)d_in[24]; sa.Bd[5] = (const float*)d_in[25];

    dim3 gg(BQ/64, NSPLIT);   // 32 x 8 = 256 CTAs

    // 1. integrate + 20-ch fluid feats
    k_prep<<<(BQ+127)/128, 128>>>(p0, v0, a, other, v0_enc);
    // 2. fused geometry + compaction + bin sort (fluid & obstacle)
    k_compact2<<<dim3(BQ/8, 2), 256>>>(box, fmask, bmask);
    // 3. steered matrices (quarter-threaded, fp16 TC segments)
    k_steer_all<<<(SQ5+255)/256, 256>>>(sa);
    // 4. stage-1 binning: fluid bin40 + obstacle bin+conv -> feats cols 0..31
    k_bin1<<<dim3(BQ, 2), 240>>>(feats, boxf, KSf+F1B);
    // 5. stage-1 GEMM + fluid finish -> feats cols 32..95
    k_gemm_mma<<<gg, 128>>>(Xh, KSh+H1A, 1984);
    k_finnl_s1<<<(BQ*32+255)/256, 256>>>();
    // 6. layer 1: 48 -> 32
    k_bin<96,4704,6><<<BQ, 288>>>(feats);
    k_gemm_mma<<<gg, 128>>>(Xh, KSh+HL1, 4704);
    k_finnl<<<(BQ*32+255)/256, 256>>>(outB, nullptr);
    // 7. layer 2: 32 -> 32, residual
    k_bin<64,3136,8><<<BQ, 256>>>(feats);
    k_gemm_mma<<<gg, 128>>>(Xh, KSh+HL2, 3136);
    k_finnl<<<(BQ*32+255)/256, 256>>>(outA, outB);
    // 8. layer 3: 32 -> 32, residual
    k_bin<64,3136,8><<<BQ, 256>>>(feats);
    k_gemm_mma<<<gg, 128>>>(Xh, KSh+HL3, 3136);
    k_finnl<<<(BQ*32+255)/256, 256>>>(outB, outA);
    // 9. layer 4 fully fused: bin + conv2 + dense + final correction (no k_bin, no X round-trip)
    k_last<<<BQ/8, 256>>>(KSf+FL4, p0, dout, half);
}